// round 16
// baseline (speedup 1.0000x reference)
#include <cuda_runtime.h>
#include <math.h>
#include <stdint.h>

#define NB   32
#define CC   256
#define C4   64
#define LL   6
#define TT   64
#define VV   25
#define EPS  1e-5f
#define SLOPE 0.2f
#define NPAIR 45

#define GS_BLOCKS (NB * CC * 400 / 256)   // 12800 gatesum blocks
#define GRID_F    (NB + GS_BLOCKS)        // 32 middle + 12800 stream

// scratch (no cudaMalloc allowed)
__device__ float g_xt[NB * CC * LL * VV];     // [n][c][l][v]
__device__ float g_gate[NB * CC * LL];        // [n][c][l]
__device__ int   g_flag[NB];                  // per-sample gate-ready flags

__constant__ int c_pv[NPAIR] = {
    1,0,20,
    0,20,12,16,2,4,8,
    12,16,2,4,8,13,17,3,5,9,
    13,17,3,5,9,14,18,6,10,
    14,18,6,10,15,19,7,11,
    15,19,7,11,21,22,23,24};
__constant__ int c_off[LL + 1] = {0,3,10,20,29,37,45};
__constant__ float c_inv_cnt[LL] = {1.f/3.f, 1.f/7.f, 1.f/10.f, 1.f/9.f, 1.f/8.f, 1.f/8.f};

__device__ __forceinline__ void cp_async4(void* dst_smem, const void* src) {
    uint32_t d = (uint32_t)__cvta_generic_to_shared(dst_smem);
    asm volatile("cp.async.ca.shared.global [%0], [%1], 4;\n" :: "r"(d), "l"(src));
}
__device__ __forceinline__ void cp_wait_all_f() {
    asm volatile("cp.async.wait_all;\n" ::: "memory");
}

// ---------------------------------------------------------------------------
// Kernel 1 (measured ~49.8us @ 81.6% DRAM): x_t[n,c,l,v] = max_t x[n,c,l,t,v]
// Also resets the per-sample flags for this replay (visible at next launch).
// ---------------------------------------------------------------------------
__global__ __launch_bounds__(128) void k_tmax(const float* __restrict__ x) {
    __shared__ float4 tile4[400];
    float* tile = reinterpret_cast<float*>(tile4);
    const int b = blockIdx.x;                 // (n*C + c)*L + l
    const float4* xb = reinterpret_cast<const float4*>(x) + (size_t)b * 400;
    const int tid = threadIdx.x;
    if (b == 0 && tid < NB) g_flag[tid] = 0;  // replay-safe flag reset
    #pragma unroll
    for (int i = 0; i < 3; i++) tile4[tid + i * 128] = xb[tid + i * 128];
    if (tid < 16) tile4[tid + 384] = xb[tid + 384];
    __syncthreads();
    if (tid < VV) {
        float m = tile[tid];
        #pragma unroll
        for (int t = 1; t < TT; t++) m = fmaxf(m, tile[t * VV + tid]);
        g_xt[(size_t)b * VV + tid] = m;
    }
}

// ---------------------------------------------------------------------------
// Kernel 2: blocks 0..31 = per-sample middle (projection/knn/EdgeConv/gate),
// publish flag; blocks 32.. = gated sum, spinning briefly on their sample's
// flag. One launch gap removed; middle hidden under the stream wave ramp.
// ---------------------------------------------------------------------------
__global__ __launch_bounds__(256, 8) void k_final(
    const float* __restrict__ x,
    const float* __restrict__ W_down, const float* __restrict__ b_down,
    const float* __restrict__ g_down, const float* __restrict__ be_down,
    const float* __restrict__ m_down, const float* __restrict__ v_down,
    const float* __restrict__ W_edge, const float* __restrict__ g_edge,
    const float* __restrict__ be_edge, const float* __restrict__ m_edge,
    const float* __restrict__ v_edge, const float* __restrict__ W_agg,
    const float* __restrict__ b_agg, float* __restrict__ out) {
    const int t = threadIdx.x;

    __shared__ float shX[10 * 256];           // per-layer gathered X
    __shared__ float parts[4 * 10 * 64];      // [g][p][o]
    __shared__ float sh_s[C4 * LL];           // [c][l]
    __shared__ float sh_G[LL * LL];
    __shared__ int   sh_idx[LL * 3];
    __shared__ float sh_e[C4 * LL];           // [o][l]

    if (blockIdx.x < NB) {
        // ================= middle for sample n =================
        const int n = blockIdx.x;
        const int o = t & 63;
        const int g = t >> 6;

        for (int l = 0; l < LL; l++) {
            const int p0 = c_off[l];
            const int cnt = c_off[l + 1] - p0;
            // gather cnt x 256 channel values for this layer (full MLP)
            const float* xb = g_xt + ((size_t)(n * CC) + t) * (LL * VV) + l * VV;
            for (int p = 0; p < cnt; p++)
                cp_async4(&shX[p * 256 + t], xb + c_pv[p0 + p]);
            cp_wait_all_f();
            __syncthreads();

            // projection: W row segment via global float4 (L1-hit after p=0)
            const float4* wr = reinterpret_cast<const float4*>(W_down)
                               + o * 64 + g * 16;
            for (int p = 0; p < cnt; p++) {
                const float4* xp = reinterpret_cast<const float4*>(
                    shX + p * 256 + g * 64);
                float a = 0.f;
                #pragma unroll
                for (int i = 0; i < 16; i++) {
                    const float4 w = wr[i];
                    const float4 xv = xp[i];
                    a += w.x * xv.x + w.y * xv.y + w.z * xv.z + w.w * xv.w;
                }
                parts[(g * 10 + p) * 64 + o] = a;
            }
            __syncthreads();

            if (t < 64) {
                const float gs  = g_down[t] * rsqrtf(v_down[t] + EPS);
                const float shb = be_down[t] - m_down[t] * gs;
                const float bd  = b_down[t];
                float ssum = 0.f;
                for (int p = 0; p < cnt; p++) {
                    const float y = (parts[p * 64 + t] + parts[(10 + p) * 64 + t] +
                                     parts[(20 + p) * 64 + t] + parts[(30 + p) * 64 + t]
                                     + bd) * gs + shb;
                    ssum += fmaxf(y, 0.f);
                }
                sh_s[t * LL + l] = ssum * c_inv_cnt[l];
            }
            __syncthreads();
        }

        // Gram matrix
        if (t < LL * LL) {
            const int i = t / LL, j = t % LL;
            float acc = 0.f;
            #pragma unroll 8
            for (int c = 0; c < C4; c++) acc += sh_s[c * LL + i] * sh_s[c * LL + j];
            sh_G[t] = acc;
        }
        __syncthreads();

        // top-3 neighbors (stable tie-break matching lax.top_k)
        if (t < LL) {
            float d[LL];
            bool used[LL];
            const float sqi = sh_G[t * LL + t];
            #pragma unroll
            for (int j = 0; j < LL; j++) {
                d[j] = 2.f * sh_G[t * LL + j] - sqi - sh_G[j * LL + j];
                used[j] = false;
            }
            #pragma unroll
            for (int k = 0; k < 3; k++) {
                float best = -INFINITY; int bi = 0;
                #pragma unroll
                for (int j = 0; j < LL; j++)
                    if (!used[j] && d[j] > best) { best = d[j]; bi = j; }
                used[bi] = true;
                sh_idx[t * 3 + k] = bi;
            }
        }
        __syncthreads();

        // EdgeConv + BN + leaky + max over k (W_edge via global float4, L2-hot)
        for (int item = t; item < LL * C4; item += 256) {
            const int oo = item & 63;
            const int l  = item >> 6;
            const float4* w14 = reinterpret_cast<const float4*>(W_edge + oo * 128);
            const int n0 = sh_idx[l * 3], n1 = sh_idx[l * 3 + 1], n2 = sh_idx[l * 3 + 2];
            float base = 0.f, a0 = 0.f, a1 = 0.f, a2 = 0.f;
            #pragma unroll 4
            for (int i = 0; i < 16; i++) {
                const float4 w = w14[i];
                const float4 w2 = w14[16 + i];
                const int c = 4 * i;
                #pragma unroll
                for (int q = 0; q < 4; q++) {
                    const float wq = (&w.x)[q];
                    base += ((&w2.x)[q] - wq) * sh_s[(c + q) * LL + l];
                    a0 += wq * sh_s[(c + q) * LL + n0];
                    a1 += wq * sh_s[(c + q) * LL + n1];
                    a2 += wq * sh_s[(c + q) * LL + n2];
                }
            }
            const float gs  = g_edge[oo] * rsqrtf(v_edge[oo] + EPS);
            const float shb = be_edge[oo] - m_edge[oo] * gs;
            float m = -INFINITY;
            float ys[3] = {a0 + base, a1 + base, a2 + base};
            #pragma unroll
            for (int k = 0; k < 3; k++) {
                float y = ys[k] * gs + shb;
                y = fmaxf(y, 0.f) + SLOPE * fminf(y, 0.f);
                m = fmaxf(m, y);
            }
            sh_e[oo * LL + l] = m;
        }
        __syncthreads();

        // att = W_agg @ e + b_agg ; gate = sigmoid
        {
            const int oc = t;
            float a[LL];
            const float bb = b_agg[oc];
            #pragma unroll
            for (int l = 0; l < LL; l++) a[l] = bb;
            const float4* wr = reinterpret_cast<const float4*>(W_agg + oc * C4);
            #pragma unroll 4
            for (int i = 0; i < 16; i++) {
                const float4 w = wr[i];
                const int c = 4 * i;
                #pragma unroll
                for (int l = 0; l < LL; l++)
                    a[l] += w.x * sh_e[c * LL + l] + w.y * sh_e[(c+1) * LL + l]
                          + w.z * sh_e[(c+2) * LL + l] + w.w * sh_e[(c+3) * LL + l];
            }
            float* gp = g_gate + ((size_t)n * CC + oc) * LL;
            #pragma unroll
            for (int l = 0; l < LL; l++)
                gp[l] = 1.f / (1.f + expf(-a[l]));
        }
        // publish
        __syncthreads();
        __threadfence();
        if (t == 0) ((volatile int*)g_flag)[n] = 1;
        return;
    }

    // ================= gated sum =================
    const int gid = blockIdx.x - NB;
    const int idx = gid * 256 + t;            // [0, 32*256*400)
    // samples touched by this block (idx window of 256 spans <=2 samples)
    if (t == 0) {
        const int n_lo = (gid * 256) / (CC * 400);
        const int n_hi = (gid * 256 + 255) / (CC * 400);
        while (((volatile int*)g_flag)[n_lo] == 0) { __nanosleep(128); }
        while (((volatile int*)g_flag)[n_hi] == 0) { __nanosleep(128); }
    }
    __syncthreads();

    const int tv4 = idx % 400;
    const int nc  = idx / 400;
    const float4* xb = reinterpret_cast<const float4*>(x) + (size_t)nc * (LL * 400) + tv4;
    const float* gp = g_gate + (size_t)nc * LL;
    float4 acc = make_float4(0.f, 0.f, 0.f, 0.f);
    #pragma unroll
    for (int l = 0; l < LL; l++) {
        const float g = gp[l];
        const float4 xv = xb[l * 400];
        acc.x += xv.x * g; acc.y += xv.y * g;
        acc.z += xv.z * g; acc.w += xv.w * g;
    }
    reinterpret_cast<float4*>(out)[(size_t)nc * 400 + tv4] = acc;
}

// ---------------------------------------------------------------------------
extern "C" void kernel_launch(void* const* d_in, const int* in_sizes, int n_in,
                              void* d_out, int out_size) {
    const float* x       = (const float*)d_in[0];
    const float* W_down  = (const float*)d_in[1];
    const float* b_down  = (const float*)d_in[2];
    const float* g_down  = (const float*)d_in[3];
    const float* be_down = (const float*)d_in[4];
    const float* m_down  = (const float*)d_in[5];
    const float* v_down  = (const float*)d_in[6];
    const float* W_edge  = (const float*)d_in[7];
    const float* g_edge  = (const float*)d_in[8];
    const float* be_edge = (const float*)d_in[9];
    const float* m_edge  = (const float*)d_in[10];
    const float* v_edge  = (const float*)d_in[11];
    const float* W_agg   = (const float*)d_in[12];
    const float* b_agg   = (const float*)d_in[13];
    float* out = (float*)d_out;

    k_tmax<<<NB * CC * LL, 128>>>(x);
    k_final<<<GRID_F, 256>>>(x, W_down, b_down, g_down, be_down, m_down, v_down,
                             W_edge, g_edge, be_edge, m_edge, v_edge,
                             W_agg, b_agg, out);
}